// round 1
// baseline (speedup 1.0000x reference)
#include <cuda_runtime.h>

// Problem constants
#define B_  2
#define T_  400
#define C_  8
#define F_  512
#define K_  40
#define P_  64
#define C2_ 64
#define TILES (B_ * T_)   // 800

// Scratch for projected (pre-IIR) real values: (B,T,K,P) = 2,048,000 floats
__device__ float g_z[B_ * T_ * K_ * P_];

// -------- shared memory layout (dynamic) --------
// phase A/B:
//   xs : float2 [8][513]   offset 0       (32832 B)   x[c][f], padded rows
//   ar : float2 [8][513]   offset 32832   (32832 B)   (a_c[f], r_c[f])
//   bm : float2 [512][40]  offset 65664   (163840 B)  band matrix, row-major in f
// total = 229504 B
// epilogue (reuses [0, 65664)):
//   bc   : float2 [40][64] offset 0       (20480 B)   band_cov[k][c2]
//   invd : float  [40]     offset 20480   (160 B)
//   ct   : float2 [64][65] offset 20640   (33280 B)   c2p transposed [c][p], padded
#define SMEM_BYTES 229504

extern __shared__ char smem[];

__global__ void __launch_bounds__(256, 1) pv_main(
    const float* __restrict__ br,  const float* __restrict__ bi,
    const float* __restrict__ bmr, const float* __restrict__ bmi,
    const float* __restrict__ pr,  const float* __restrict__ pi)
{
    float2* xs  = (float2*)(smem);
    float2* ar  = (float2*)(smem + 32832);
    float2* bms = (float2*)(smem + 65664);

    const int tid  = threadIdx.x;
    const int tile = blockIdx.x;

    // ---- Phase A: load inputs to smem ----
    const float* brt = br + (size_t)tile * (C_ * F_);
    const float* bit = bi + (size_t)tile * (C_ * F_);
    #pragma unroll 4
    for (int idx = tid; idx < C_ * F_; idx += 256) {
        int c = idx >> 9, f = idx & 511;
        xs[c * 513 + f] = make_float2(brt[idx], bit[idx]);
    }
    #pragma unroll 4
    for (int idx = tid; idx < F_ * K_; idx += 256) {
        bms[idx] = make_float2(bmr[idx], bmi[idx]);
    }
    __syncthreads();

    // ---- per-(c,f) norms and rsqrt ----
    #pragma unroll 4
    for (int idx = tid; idx < C_ * F_; idx += 256) {
        int c = idx >> 9, f = idx & 511;
        float2 v = xs[c * 513 + f];
        float n = v.x * v.x + v.y * v.y;
        float r = rsqrtf(fmaxf(n, 1e-37f));
        ar[c * 513 + f] = make_float2(n, r);    // stash (n, 1/|x|)
    }
    __syncthreads();

    // ---- per-f trace normalisation: a_c = |x_c| * rsqrt(clip(trace)) ----
    for (int f = tid; f < F_; f += 256) {
        float tr = 0.f;
        #pragma unroll
        for (int c = 0; c < C_; c++) tr += ar[c * 513 + f].x;
        float sit = rsqrtf(fmaxf(tr, 1e-20f));
        #pragma unroll
        for (int c = 0; c < C_; c++) {
            float2 v = ar[c * 513 + f];
            // m = n * rsqrt(n) = sqrt(n);  a = m * sit
            ar[c * 513 + f] = make_float2(v.x * v.y * sit, v.y);
        }
    }
    __syncthreads();

    // ---- Phase B: fused adj + band-projection GEMM ----
    // warp w owns i = w; lane -> (j = lane>>2, k-group = lane&3)
    const int w    = tid >> 5;
    const int lane = tid & 31;
    const int jch  = lane >> 2;
    const int kg   = lane & 3;
    const int ich  = w;
    const bool isdiag = (ich == jch);

    const float2* xi = xs + ich * 513;
    const float2* xj = xs + jch * 513;
    const float2* ai = ar + ich * 513;
    const float2* aj = ar + jch * 513;

    float2 acc[10];
    #pragma unroll
    for (int kk = 0; kk < 10; kk++) acc[kk] = make_float2(0.f, 0.f);

    for (int f = 0; f < F_; f++) {
        int fm = min(max(f - 1, 0), 509);   // edge-padded lag index
        int fp = fm + 2;

        float2 xim = xi[fm], xjm = xj[fm];
        float2 xip = xi[fp], xjp = xj[fp];

        float aaf = ai[f].x  * aj[f].x;     // m_i m_j * invtr
        float rrm = ai[fm].y * aj[fm].y;    // 1/(m_i m_j) at f-1
        float rrp = ai[fp].y * aj[fp].y;    // 1/(m_i m_j) at f+1

        // chat[f] = x_i * conj(x_j)
        float cmre = xim.x * xjm.x + xim.y * xjm.y;
        float cmim = xim.y * xjm.x - xim.x * xjm.y;
        float cpre = xip.x * xjp.x + xip.y * xjp.y;
        float cpim = xip.y * xjp.x - xip.x * xjp.y;

        // q = conj(chat[fm]) * chat[fp]
        float qre = cmre * cpre + cmim * cpim;
        float qim = cmre * cpim - cmim * cpre;

        float s = aaf * rrm * rrp;
        float adre, adim;
        if (isdiag) { adre = aaf; adim = 0.f; }      // diag keeps original c (real)
        else        { adre = s * qre; adim = s * qim; }

        const float4* bp = (const float4*)(bms + f * K_ + kg * 10);
        #pragma unroll
        for (int kk2 = 0; kk2 < 5; kk2++) {
            float4 bb = bp[kk2];
            acc[2 * kk2].x     += adre * bb.x - adim * bb.y;
            acc[2 * kk2].y     += adre * bb.y + adim * bb.x;
            acc[2 * kk2 + 1].x += adre * bb.z - adim * bb.w;
            acc[2 * kk2 + 1].y += adre * bb.w + adim * bb.z;
        }
    }

    // ---- Epilogue: dsum normalisation + cov->pv projection (real part) ----
    __syncthreads();   // done reading xs/ar; reuse that smem
    float2* bc   = (float2*)(smem);
    float*  invd = (float*)(smem + 20480);
    float2* ct   = (float2*)(smem + 20640);

    const int c2 = w * 8 + jch;
    #pragma unroll
    for (int kk = 0; kk < 10; kk++)
        bc[(kg * 10 + kk) * C2_ + c2] = acc[kk];
    __syncthreads();

    if (tid < K_) {
        float s = 0.f;
        #pragma unroll
        for (int d = 0; d < C_; d++) s += bc[tid * C2_ + d * 9].x;
        invd[tid] = 1.0f / fmaxf(s, 1e-20f);
    }
    // load c2p transposed into smem: ct[c][p]
    #pragma unroll 4
    for (int idx = tid; idx < P_ * C2_; idx += 256) {
        int p = idx >> 6, c = idx & 63;
        ct[c * 65 + p] = make_float2(pr[idx], pi[idx]);
    }
    __syncthreads();

    // thread -> fixed p, k in {k0 + 4r}
    const int p  = tid & 63;
    const int k0 = tid >> 6;   // 0..3 (constant within a warp)
    float out[10];
    #pragma unroll
    for (int r = 0; r < 10; r++) out[r] = 0.f;

    for (int c = 0; c < C2_; c++) {
        float2 m = ct[c * 65 + p];
        #pragma unroll
        for (int r = 0; r < 10; r++) {
            float2 v = bc[(k0 + 4 * r) * C2_ + c];   // broadcast within warp
            out[r] += m.x * v.x - m.y * v.y;
        }
    }
    float* zt = g_z + (size_t)tile * (K_ * P_);
    #pragma unroll
    for (int r = 0; r < 10; r++) {
        int k = k0 + 4 * r;
        zt[k * P_ + p] = out[r] * invd[k];
    }
}

// ---- Kernel 2: first-order IIR over frames (linear map commutes past projection) ----
__global__ void __launch_bounds__(256) iir_k(const float* __restrict__ tau,
                                             float* __restrict__ out)
{
    int tid = blockIdx.x * blockDim.x + threadIdx.x;
    if (tid >= B_ * K_ * P_) return;
    int p = tid & 63;
    int k = (tid >> 6) % K_;
    int b = tid / (K_ * P_);

    float a  = tau[k];
    float om = 1.0f - a;
    float y  = 0.f;
    size_t base = (size_t)b * T_ * K_ * P_ + (size_t)k * P_ + p;
    const size_t stride = (size_t)K_ * P_;

    #pragma unroll 4
    for (int t = 0; t < T_; t++) {
        float x = g_z[base + (size_t)t * stride];
        y = a * y + om * x;
        out[base + (size_t)t * stride] = y;
    }
}

extern "C" void kernel_launch(void* const* d_in, const int* in_sizes, int n_in,
                              void* d_out, int out_size)
{
    const float* br  = (const float*)d_in[0];
    const float* bi  = (const float*)d_in[1];
    const float* bmr = (const float*)d_in[2];
    const float* bmi = (const float*)d_in[3];
    const float* pr  = (const float*)d_in[4];
    const float* pi  = (const float*)d_in[5];
    const float* tau = (const float*)d_in[6];

    cudaFuncSetAttribute(pv_main, cudaFuncAttributeMaxDynamicSharedMemorySize, SMEM_BYTES);

    pv_main<<<TILES, 256, SMEM_BYTES>>>(br, bi, bmr, bmi, pr, pi);
    iir_k<<<(B_ * K_ * P_ + 255) / 256, 256>>>(tau, (float*)d_out);
}

// round 2
// speedup vs baseline: 2.3796x; 2.3796x over previous
#include <cuda_runtime.h>

#define TILES 800
#define NTHR  320   // 10 warps: warp = k-group (4 ks), lane = pair item

__device__ float g_z[2 * 400 * 40 * 64];   // pre-IIR projected values (B,T,K,P)
__device__ float g_cf[2 * 8 * 40 * 64];    // chunk-final y
__device__ float g_ci[2 * 8 * 40 * 64];    // chunk carry-in

// item table: bits[0:8)=i, [8:16)=j, bit16 = diag-pseudo-pair flag
__constant__ unsigned PAIR_TBL[32] = {
  0x0100,0x0200,0x0300,0x0400,0x0500,0x0600,0x0700,
  0x0201,0x0301,0x0401,0x0501,0x0601,0x0701,
  0x0302,0x0402,0x0502,0x0602,0x0702,
  0x0403,0x0503,0x0603,0x0703,
  0x0504,0x0604,0x0704,
  0x0605,0x0705,
  0x0706,
  0x10100,0x10302,0x10504,0x10706
};

// ---- smem layout (bytes) ----
// [0,32768)      xs float2[8][512]; later adjch float2[128][32]; later bc/invd/ct
// [32768,65856)  gs float2[8][517]  (517 stride -> conflict-free channel access)
// [65856,229696) bm float2[512][40]
#define OFF_XS 0
#define OFF_GS 32768
#define OFF_BM 65856
#define SMEM_TOTAL 229696

__device__ __forceinline__ unsigned long long pack2(float a, float b) {
    unsigned long long r;
    asm("mov.b64 %0, {%1,%2};" : "=l"(r) : "f"(a), "f"(b));
    return r;
}
__device__ __forceinline__ void fma2(unsigned long long& acc,
                                     unsigned long long a, unsigned long long b) {
    asm("fma.rn.f32x2 %0, %1, %2, %0;" : "+l"(acc) : "l"(a), "l"(b));
}
__device__ __forceinline__ void unpack2(unsigned long long x, float& lo, float& hi) {
    asm("mov.b64 {%0,%1}, %2;" : "=f"(lo), "=f"(hi) : "l"(x));
}

extern __shared__ char sm_[];

__global__ void __launch_bounds__(NTHR, 1) pv_main(
    const float* __restrict__ br,  const float* __restrict__ bi,
    const float* __restrict__ bmr, const float* __restrict__ bmi,
    const float* __restrict__ pr,  const float* __restrict__ pi)
{
    float2* xs  = (float2*)(sm_ + OFF_XS);
    float2* gs  = (float2*)(sm_ + OFF_GS);
    float2* bms = (float2*)(sm_ + OFF_BM);

    const int tid  = threadIdx.x;
    const int tile = blockIdx.x;
    const int lane = tid & 31;
    const int w    = tid >> 5;           // warp = k-group (k = 4w..4w+3)

    // ---- Phase A: vectorized loads ----
    const float4* br4 = (const float4*)(br + (size_t)tile * 4096);
    const float4* bi4 = (const float4*)(bi + (size_t)tile * 4096);
    for (int idx = tid; idx < 1024; idx += NTHR) {
        float4 a = br4[idx], b = bi4[idx];
        int o = idx * 4;
        xs[o]   = make_float2(a.x, b.x); xs[o+1] = make_float2(a.y, b.y);
        xs[o+2] = make_float2(a.z, b.z); xs[o+3] = make_float2(a.w, b.w);
    }
    const float4* mr4 = (const float4*)bmr;
    const float4* mi4 = (const float4*)bmi;
    for (int idx = tid; idx < 5120; idx += NTHR) {
        float4 a = mr4[idx], b = mi4[idx];
        int o = idx * 4;
        bms[o]   = make_float2(a.x, b.x); bms[o+1] = make_float2(a.y, b.y);
        bms[o+2] = make_float2(a.z, b.z); bms[o+3] = make_float2(a.w, b.w);
    }
    __syncthreads();

    // ---- step 1: per (c,f): (|x|^2, rsqrt) into gs ----
    #pragma unroll
    for (int r = 0; r < 13; r++) {
        int t = tid + r * NTHR;
        if (t < 4096) {
            int c = t >> 9, f = t & 511;
            float2 v = xs[c * 512 + f];
            float n = v.x * v.x + v.y * v.y;
            gs[c * 517 + f] = make_float2(n, rsqrtf(fmaxf(n, 1e-37f)));
        }
    }
    __syncthreads();

    // ---- step 2: trace-normalised amplitude a_c = |x_c| * rsqrt(clip(tr)) ----
    for (int f = tid; f < 512; f += NTHR) {
        float tr = 0.f;
        #pragma unroll
        for (int c = 0; c < 8; c++) tr += gs[c * 517 + f].x;
        float sit = rsqrtf(fmaxf(tr, 1e-20f));
        #pragma unroll
        for (int c = 0; c < 8; c++) {
            float2 v = gs[c * 517 + f];
            gs[c * 517 + f].x = v.x * v.y * sit;   // a = n * rsqrt(n) * sit
        }
    }
    __syncthreads();

    // ---- step 3: g_c[f] = a_c[f] * r[fm] * r[fp] * conj(x[fm]) * x[fp] ----
    float2 gv[13];
    #pragma unroll
    for (int r = 0; r < 13; r++) {
        int t = tid + r * NTHR;
        if (t < 4096) {
            int c = t >> 9, f = t & 511;
            int fm = min(max(f - 1, 0), 509), fp = fm + 2;
            float a  = gs[c * 517 + f].x;
            float rm = gs[c * 517 + fm].y, rp = gs[c * 517 + fp].y;
            float2 xm = xs[c * 512 + fm], xp = xs[c * 512 + fp];
            float tre = xm.x * xp.x + xm.y * xp.y;
            float tim = xm.x * xp.y - xm.y * xp.x;
            float s = a * rm * rp;
            gv[r] = make_float2(s * tre, s * tim);
        }
    }
    __syncthreads();
    #pragma unroll
    for (int r = 0; r < 13; r++) {
        int t = tid + r * NTHR;
        if (t < 4096) { int c = t >> 9, f = t & 511; gs[c * 517 + f] = gv[r]; }
    }
    __syncthreads();   // xs dead from here; adjch reuses its space

    // ---- main fused loop: adj materialize (chunked) + packed GEMM ----
    const unsigned e   = PAIR_TBL[lane];
    const int iCh = e & 255, jCh = (e >> 8) & 255;
    const bool dg = (e & 0x10000u) != 0;

    float2* adjch = (float2*)(sm_ + OFF_XS);             // [128][32]
    const ulonglong2* bm2 = (const ulonglong2*)(sm_ + OFF_BM);

    unsigned long long accA0=0, accA1=0, accA2=0, accA3=0;
    unsigned long long accB0=0, accB1=0, accB2=0, accB3=0;

    for (int ch = 0; ch < 4; ch++) {
        // adj phase: item == lane for every round (stride 320 ≡ 0 mod 32)
        #pragma unroll
        for (int r = 0; r < 13; r++) {
            int fc = w + r * 10;
            if (fc < 128) {
                int f = ch * 128 + fc;
                float2 gi = gs[iCh * 517 + f], gj = gs[jCh * 517 + f];
                float u, v;
                if (dg) { u = gi.x*gi.x + gi.y*gi.y;  v = gj.x*gj.x + gj.y*gj.y; }
                else    { u = gi.x*gj.x + gi.y*gj.y;  v = gi.y*gj.x - gi.x*gj.y; }
                adjch[fc * 32 + lane] = make_float2(u, v);
            }
        }
        __syncthreads();

        const int fbase = ch * 128;
        #pragma unroll 2
        for (int fc = 0; fc < 128; fc++) {
            float2 uv = adjch[fc * 32 + lane];
            unsigned long long uu = pack2(uv.x, uv.x);
            unsigned long long vv = pack2(uv.y, uv.y);
            int f = fbase + fc;
            ulonglong2 q0 = bm2[f * 20 + 2 * w];
            ulonglong2 q1 = bm2[f * 20 + 2 * w + 1];
            fma2(accA0, uu, q0.x); fma2(accB0, vv, q0.x);
            fma2(accA1, uu, q0.y); fma2(accB1, vv, q0.y);
            fma2(accA2, uu, q1.x); fma2(accB2, vv, q1.x);
            fma2(accA3, uu, q1.y); fma2(accB3, vv, q1.y);
        }
        __syncthreads();
    }

    // ---- epilogue: assemble band_cov, dsum, cov->pv projection ----
    float2* bc   = (float2*)(sm_ + OFF_XS);              // [40][64]
    float*  invd = (float*)(sm_ + OFF_XS + 20480);
    float2* ct   = (float2*)(sm_ + OFF_XS + 20736);      // [64][65]

    {
        unsigned long long A[4] = {accA0, accA1, accA2, accA3};
        unsigned long long Bv[4] = {accB0, accB1, accB2, accB3};
        #pragma unroll
        for (int kk = 0; kk < 4; kk++) {
            float S1, S3, S4, S2;
            unpack2(A[kk], S1, S3);
            unpack2(Bv[kk], S4, S2);
            int k = 4 * w + kk;
            if (dg) {
                bc[k * 64 + iCh * 9] = make_float2(S1, S3);
                bc[k * 64 + jCh * 9] = make_float2(S4, S2);
            } else {
                bc[k * 64 + iCh * 8 + jCh] = make_float2(S1 - S2, S3 + S4);
                bc[k * 64 + jCh * 8 + iCh] = make_float2(S1 + S2, S3 - S4);
            }
        }
    }
    __syncthreads();

    if (tid < 40) {
        float s = 0.f;
        #pragma unroll
        for (int d = 0; d < 8; d++) s += bc[tid * 64 + d * 9].x;
        invd[tid] = 1.0f / fmaxf(s, 1e-20f);
    }
    for (int idx = tid; idx < 4096; idx += NTHR) {
        int p = idx >> 6, c = idx & 63;
        ct[c * 65 + p] = make_float2(pr[idx], pi[idx]);
    }
    __syncthreads();

    const unsigned long long* ctu = (const unsigned long long*)ct;
    const unsigned long long* bcu = (const unsigned long long*)bc;
    const int p  = tid & 63;
    const int kq = tid >> 6;         // 0..4, warp-uniform
    unsigned long long acc[8] = {0,0,0,0,0,0,0,0};
    for (int c = 0; c < 64; c++) {
        unsigned long long m = ctu[c * 65 + p];
        #pragma unroll
        for (int r = 0; r < 8; r++)
            fma2(acc[r], m, bcu[(kq + 5 * r) * 64 + c]);
    }
    float* zt = g_z + (size_t)tile * 2560;
    #pragma unroll
    for (int r = 0; r < 8; r++) {
        int k = kq + 5 * r;
        float lo, hi; unpack2(acc[r], lo, hi);
        zt[k * 64 + p] = (lo - hi) * invd[k];   // Re(c2p · y), dsum-normalised
    }
}

// ---- IIR as a blocked scan: local scan / carry combine / fixup ----
__global__ void __launch_bounds__(256) iir_local(const float* __restrict__ tau,
                                                 float* __restrict__ out)
{
    int tid = blockIdx.x * 256 + threadIdx.x;   // 40960 = B*K*P*8
    int p = tid & 63;
    int k = (tid >> 6) % 40;
    int ch = (tid / 2560) & 7;
    int b = tid / 20480;
    float a = tau[k], om = 1.0f - a;
    size_t base = ((size_t)b * 400 + ch * 50) * 2560 + k * 64 + p;
    float y = 0.f;
    #pragma unroll 5
    for (int i = 0; i < 50; i++) {
        y = a * y + om * g_z[base + (size_t)i * 2560];
        out[base + (size_t)i * 2560] = y;
    }
    g_cf[((b * 8 + ch) * 40 + k) * 64 + p] = y;
}

__global__ void __launch_bounds__(256) iir_carry(const float* __restrict__ tau)
{
    int tid = blockIdx.x * 256 + threadIdx.x;   // 5120 = B*K*P
    int p = tid & 63, k = (tid >> 6) % 40, b = tid / 2560;
    float a = tau[k];
    float a50 = powf(a, 50.f);
    float prev = 0.f;
    #pragma unroll
    for (int ch = 0; ch < 8; ch++) {
        int idx = ((b * 8 + ch) * 40 + k) * 64 + p;
        g_ci[idx] = prev;
        prev = g_cf[idx] + a50 * prev;
    }
}

__global__ void __launch_bounds__(256) iir_fix(const float* __restrict__ tau,
                                               float* __restrict__ out)
{
    int tid = blockIdx.x * 256 + threadIdx.x;
    int p = tid & 63, k = (tid >> 6) % 40;
    int ch = (tid / 2560) & 7, b = tid / 20480;
    if (ch == 0) return;
    float c = g_ci[((b * 8 + ch) * 40 + k) * 64 + p];
    float a = tau[k];
    size_t base = ((size_t)b * 400 + ch * 50) * 2560 + k * 64 + p;
    float t = a * c;
    #pragma unroll 5
    for (int i = 0; i < 50; i++) {
        out[base + (size_t)i * 2560] += t;   // y = local + c * a^(i+1)
        t *= a;
    }
}

extern "C" void kernel_launch(void* const* d_in, const int* in_sizes, int n_in,
                              void* d_out, int out_size)
{
    const float* br  = (const float*)d_in[0];
    const float* bi  = (const float*)d_in[1];
    const float* bmr = (const float*)d_in[2];
    const float* bmi = (const float*)d_in[3];
    const float* pr  = (const float*)d_in[4];
    const float* pi  = (const float*)d_in[5];
    const float* tau = (const float*)d_in[6];

    cudaFuncSetAttribute(pv_main, cudaFuncAttributeMaxDynamicSharedMemorySize, SMEM_TOTAL);

    pv_main<<<TILES, NTHR, SMEM_TOTAL>>>(br, bi, bmr, bmi, pr, pi);
    iir_local<<<160, 256>>>(tau, (float*)d_out);
    iir_carry<<<20, 256>>>(tau);
    iir_fix<<<160, 256>>>(tau, (float*)d_out);
}